// round 3
// baseline (speedup 1.0000x reference)
#include <cuda_runtime.h>
#include <math.h>
#include <stdint.h>

#define Bv 64
#define Nv 16384
#define Mv 64
#define Cv 256
#define GAMMA_C 0.95f
#define EPS_C 1e-16f

// ---------------- device scratch (no allocation allowed) ----------------
__device__ float g_k[Bv * Mv];
__device__ float g_knorm[Bv];
__device__ float g_beta[Bv];
__device__ float g_g[Bv];
__device__ float g_z[(size_t)Bv * Nv];   // beta * sim
__device__ float g_ww[(size_t)Bv * Nv];  // w_w

// ---------------- K0: o = emb @ W^T + b; derive k, ||k||, beta, g -------
__global__ void k0_head(const float* __restrict__ emb,
                        const float* __restrict__ W,
                        const float* __restrict__ bias) {
    int bb = blockIdx.x;           // batch
    int tid = threadIdx.x;         // 256 threads
    __shared__ float se[Cv];
    __shared__ float so[Mv + 2];
    se[tid] = emb[bb * Cv + tid];
    __syncthreads();

    int warp = tid >> 5, lane = tid & 31;
    for (int j = warp; j < Mv + 2; j += 8) {
        const float* wrow = W + j * Cv;
        float s = 0.f;
        #pragma unroll
        for (int c = lane; c < Cv; c += 32) s += wrow[c] * se[c];
        #pragma unroll
        for (int o = 16; o; o >>= 1) s += __shfl_down_sync(0xffffffffu, s, o);
        if (lane == 0) so[j] = s + bias[j];
    }
    __syncthreads();

    if (tid < Mv) g_k[bb * Mv + tid] = so[tid];
    if (tid == 0) {
        float ss = 0.f;
        #pragma unroll
        for (int m = 0; m < Mv; m++) ss += so[m] * so[m];
        g_knorm[bb] = sqrtf(ss);
        float x = so[Mv];
        // numerically stable softplus (matches jax.nn.softplus)
        float beta = (x > 0.f) ? (x + log1pf(expf(-x))) : log1pf(expf(x));
        g_beta[bb] = beta;
        g_g[bb] = 1.f / (1.f + expf(-so[Mv + 1]));
    }
}

// ---------------- K1: fused similarity + w_w + new_memory ---------------
// 256 threads; 16 threads per memory row (float4 each); 64 rows per block.
__global__ void __launch_bounds__(256) k1_fused(const float* __restrict__ mem,
                                                const float* __restrict__ w_prev,
                                                float* __restrict__ out_newmem) {
    int bb = blockIdx.y;
    int rowBase = blockIdx.x * 64;
    int tid = threadIdx.x;

    __shared__ float sk[Mv];
    __shared__ float sconst[3];  // beta, g, knorm
    if (tid < Mv) sk[tid] = g_k[bb * Mv + tid];
    if (tid == 0) { sconst[0] = g_beta[bb]; sconst[1] = g_g[bb]; sconst[2] = g_knorm[bb]; }
    __syncthreads();

    int grp = tid >> 4;        // 0..15 (row group within block)
    int lane16 = tid & 15;     // lane within row group
    float4 k4 = ((const float4*)sk)[lane16];
    float beta = sconst[0], g = sconst[1], knorm = sconst[2];

    const float* wp1 = w_prev + ((size_t)bb * 3 + 1) * Nv;  // w_r_prev
    const float* wp2 = w_prev + ((size_t)bb * 3 + 2) * Nv;  // w_lu_prev

    #pragma unroll
    for (int it = 0; it < 4; it++) {
        int n = rowBase + it * 16 + grp;
        size_t off = ((size_t)bb * Nv + n) * Mv + lane16 * 4;
        float4 v = *(const float4*)(mem + off);
        float dot = v.x * k4.x + v.y * k4.y + v.z * k4.z + v.w * k4.w;
        float ss  = v.x * v.x + v.y * v.y + v.z * v.z + v.w * v.w;
        #pragma unroll
        for (int o = 8; o; o >>= 1) {
            dot += __shfl_down_sync(0xffffffffu, dot, o, 16);
            ss  += __shfl_down_sync(0xffffffffu, ss,  o, 16);
        }
        float ww = 0.f;
        if (lane16 == 0) {
            float rn = sqrtf(ss);
            float sim = dot / (knorm * rn + EPS_C);
            g_z[(size_t)bb * Nv + n] = beta * sim;
            ww = g * wp1[n] + (1.f - g) * wp2[n];
            g_ww[(size_t)bb * Nv + n] = ww;
        }
        ww = __shfl_sync(0xffffffffu, ww, 0, 16);  // broadcast within group
        float4 o4;
        o4.x = v.x + ww * k4.x;
        o4.y = v.y + ww * k4.y;
        o4.z = v.z + ww * k4.z;
        o4.w = v.w + ww * k4.w;
        *(float4*)(out_newmem + off) = o4;
    }
}

// ---------------- K2: per-batch softmax + w_u + top-n one-hot -----------
__global__ void __launch_bounds__(1024) k2_weights(const float* __restrict__ w_prev,
                                                   const int* __restrict__ n_ptr,
                                                   float* __restrict__ out_w) {
    int bb = blockIdx.x;
    int tid = threadIdx.x;  // 1024, each handles 16 elems (stride 1024)

    const float* z  = g_z  + (size_t)bb * Nv;
    const float* wwp = g_ww + (size_t)bb * Nv;
    const float* wp0 = w_prev + (size_t)bb * 3 * Nv;   // w_u_prev
    float* ou  = out_w + (size_t)bb * 3 * Nv;          // w_u
    float* orr = ou + Nv;                               // w_r
    float* olu = orr + Nv;                              // w_lu

    __shared__ float sred[32];
    __shared__ unsigned long long ured[32];
    __shared__ int sel[32];

    // --- load z, max ---
    float zv[16];
    float lmax = -INFINITY;
    #pragma unroll
    for (int j = 0; j < 16; j++) {
        zv[j] = z[tid + j * 1024];
        lmax = fmaxf(lmax, zv[j]);
    }
    #pragma unroll
    for (int o = 16; o; o >>= 1) lmax = fmaxf(lmax, __shfl_down_sync(0xffffffffu, lmax, o));
    if ((tid & 31) == 0) sred[tid >> 5] = lmax;
    __syncthreads();
    if (tid < 32) {
        float v = sred[tid];
        #pragma unroll
        for (int o = 16; o; o >>= 1) v = fmaxf(v, __shfl_down_sync(0xffffffffu, v, o));
        if (tid == 0) sred[0] = v;
    }
    __syncthreads();
    float mx = sred[0];
    __syncthreads();

    // --- sum exp ---
    float ev[16];
    float lsum = 0.f;
    #pragma unroll
    for (int j = 0; j < 16; j++) { ev[j] = expf(zv[j] - mx); lsum += ev[j]; }
    #pragma unroll
    for (int o = 16; o; o >>= 1) lsum += __shfl_down_sync(0xffffffffu, lsum, o);
    if ((tid & 31) == 0) sred[tid >> 5] = lsum;
    __syncthreads();
    if (tid < 32) {
        float v = sred[tid];
        #pragma unroll
        for (int o = 16; o; o >>= 1) v += __shfl_down_sync(0xffffffffu, v, o);
        if (tid == 0) sred[0] = v;
    }
    __syncthreads();
    float inv = 1.f / sred[0];

    // --- w_r, w_u, zero w_lu ---
    float uu[16];
    #pragma unroll
    for (int j = 0; j < 16; j++) {
        int n = tid + j * 1024;
        float wr = ev[j] * inv;
        float u = GAMMA_C * wp0[n] + wr + wwp[n];
        ou[n] = u;
        orr[n] = wr;
        olu[n] = 0.f;
        uu[j] = u;
    }
    __syncthreads();

    // --- top-n smallest w_u (ties -> lowest index, matches jax top_k) ---
    int topn = *n_ptr;
    if (topn > 32) topn = 32;
    for (int it = 0; it < topn; it++) {
        unsigned long long best = ~0ull;
        #pragma unroll
        for (int j = 0; j < 16; j++) {
            int n = tid + j * 1024;
            bool skip = false;
            for (int s = 0; s < it; s++) if (sel[s] == n) skip = true;
            if (!skip) {
                unsigned ub = __float_as_uint(uu[j]);
                ub = (ub & 0x80000000u) ? ~ub : (ub | 0x80000000u);
                unsigned long long key = ((unsigned long long)ub << 32) | (unsigned)n;
                if (key < best) best = key;
            }
        }
        #pragma unroll
        for (int o = 16; o; o >>= 1) {
            unsigned long long v = __shfl_down_sync(0xffffffffu, best, o);
            if (v < best) best = v;
        }
        if ((tid & 31) == 0) ured[tid >> 5] = best;
        __syncthreads();
        if (tid < 32) {
            unsigned long long v = ured[tid];
            #pragma unroll
            for (int o = 16; o; o >>= 1) {
                unsigned long long v2 = __shfl_down_sync(0xffffffffu, v, o);
                if (v2 < v) v = v2;
            }
            if (tid == 0) {
                int idx = (int)(v & 0xffffffffu);
                sel[it] = idx;
                olu[idx] = 1.0f;
            }
        }
        __syncthreads();
    }
}

// ---------------- launch --------------------------------------------------
extern "C" void kernel_launch(void* const* d_in, const int* in_sizes, int n_in,
                              void* d_out, int out_size) {
    const float* emb    = (const float*)d_in[0];  // (B, C)
    const float* w_prev = (const float*)d_in[1];  // (B, 3, N)
    const float* mem    = (const float*)d_in[2];  // (B, N, M)
    const float* W      = (const float*)d_in[3];  // (M+2, C)
    const float* bias   = (const float*)d_in[4];  // (M+2,)
    const int*   n_ptr  = (const int*)d_in[5];    // scalar n

    float* out_w      = (float*)d_out;                       // (B, 3, N)
    float* out_newmem = out_w + (size_t)Bv * 3 * Nv;         // (B, N, M)

    k0_head<<<Bv, 256>>>(emb, W, bias);
    dim3 g1(Nv / 64, Bv);
    k1_fused<<<g1, 256>>>(mem, w_prev, out_newmem);
    k2_weights<<<Bv, 1024>>>(w_prev, n_ptr, out_w);
}

// round 5
// speedup vs baseline: 1.0094x; 1.0094x over previous
#include <cuda_runtime.h>
#include <math.h>
#include <stdint.h>

#define Bv 64
#define Nv 16384
#define Mv 64
#define Cv 256
#define GAMMA_C 0.95f
#define EPS_C 1e-16f
#define CHUNKS 16                 // chunks per batch in k2b
#define CHUNK_ELEMS (Nv / CHUNKS) // 1024
#define MAXTOPN 16

// ---------------- device scratch (no allocation allowed) ----------------
__device__ float g_k[Bv * Mv];
__device__ float g_beta[Bv];
__device__ float g_g[Bv];
__device__ float g_e[(size_t)Bv * Nv];    // exp(beta * sim)
__device__ float g_ww[(size_t)Bv * Nv];   // w_w
__device__ float g_pexp[Bv * 256];        // per-k1-block partial sum of exp
__device__ unsigned long long g_cand[Bv * CHUNKS * MAXTOPN];

// ---------------- K0: o[j,b] = W[j]·emb[b] + b[j] ------------------------
// grid (66, 64), 256 threads: one dot product per block, tree-reduced.
__global__ void __launch_bounds__(256) k0_head(const float* __restrict__ emb,
                                               const float* __restrict__ W,
                                               const float* __restrict__ bias) {
    int j  = blockIdx.x;   // 0..65
    int bb = blockIdx.y;   // batch
    int tid = threadIdx.x;
    int warp = tid >> 5, lane = tid & 31;

    float s = W[j * Cv + tid] * emb[bb * Cv + tid];
    #pragma unroll
    for (int o = 16; o; o >>= 1) s += __shfl_down_sync(0xffffffffu, s, o);
    __shared__ float sh[8];
    if (lane == 0) sh[warp] = s;
    __syncthreads();
    if (tid == 0) {
        float t = 0.f;
        #pragma unroll
        for (int i = 0; i < 8; i++) t += sh[i];
        t += bias[j];
        if (j < Mv) {
            g_k[bb * Mv + j] = t;
        } else if (j == Mv) {
            // stable softplus
            g_beta[bb] = (t > 0.f) ? (t + log1pf(expf(-t))) : log1pf(expf(t));
        } else {
            g_g[bb] = 1.f / (1.f + expf(-t));
        }
    }
}

// ---------------- K1: fused similarity + exp + w_w + new_memory ----------
// 256 threads; 16 threads per memory row (float4 each); 64 rows per block.
__global__ void __launch_bounds__(256) k1_fused(const float* __restrict__ mem,
                                                const float* __restrict__ w_prev,
                                                float* __restrict__ out_newmem) {
    int bb = blockIdx.y;
    int rowBase = blockIdx.x * 64;
    int tid = threadIdx.x;

    __shared__ float sk[Mv];
    __shared__ float sconst[2];  // beta, g
    __shared__ float sh16[16];
    if (tid < Mv) sk[tid] = g_k[bb * Mv + tid];
    if (tid == 0) { sconst[0] = g_beta[bb]; sconst[1] = g_g[bb]; }
    __syncthreads();

    int grp = tid >> 4;        // 0..15 (row group within block)
    int lane16 = tid & 15;     // lane within row group
    float4 k4 = ((const float4*)sk)[lane16];
    float beta = sconst[0], g = sconst[1];

    // knorm from the shared k vector: 4 shuffles within each 16-lane group
    float kk = k4.x * k4.x + k4.y * k4.y + k4.z * k4.z + k4.w * k4.w;
    #pragma unroll
    for (int o = 8; o; o >>= 1) kk += __shfl_down_sync(0xffffffffu, kk, o, 16);
    float knorm = sqrtf(__shfl_sync(0xffffffffu, kk, 0, 16));

    const float* wp1 = w_prev + ((size_t)bb * 3 + 1) * Nv;  // w_r_prev
    const float* wp2 = w_prev + ((size_t)bb * 3 + 2) * Nv;  // w_lu_prev

    float esum = 0.f;
    #pragma unroll
    for (int it = 0; it < 4; it++) {
        int n = rowBase + it * 16 + grp;
        size_t off = ((size_t)bb * Nv + n) * Mv + lane16 * 4;
        float4 v = *(const float4*)(mem + off);
        float dot = v.x * k4.x + v.y * k4.y + v.z * k4.z + v.w * k4.w;
        float ss  = v.x * v.x + v.y * v.y + v.z * v.z + v.w * v.w;
        #pragma unroll
        for (int o = 8; o; o >>= 1) {
            dot += __shfl_down_sync(0xffffffffu, dot, o, 16);
            ss  += __shfl_down_sync(0xffffffffu, ss,  o, 16);
        }
        float ww = 0.f;
        if (lane16 == 0) {
            float rn = sqrtf(ss);
            float sim = dot / (knorm * rn + EPS_C);
            float e = expf(beta * sim);   // no max-sub: |beta*sim| small, safe
            g_e[(size_t)bb * Nv + n] = e;
            esum += e;
            ww = g * wp1[n] + (1.f - g) * wp2[n];
            g_ww[(size_t)bb * Nv + n] = ww;
        }
        ww = __shfl_sync(0xffffffffu, ww, 0, 16);  // broadcast within group
        float4 o4;
        o4.x = v.x + ww * k4.x;
        o4.y = v.y + ww * k4.y;
        o4.z = v.z + ww * k4.z;
        o4.w = v.w + ww * k4.w;
        *(float4*)(out_newmem + off) = o4;
    }

    // deterministic per-block partial sum of exp
    if (lane16 == 0) sh16[grp] = esum;
    __syncthreads();
    if (tid == 0) {
        float s = 0.f;
        #pragma unroll
        for (int i = 0; i < 16; i++) s += sh16[i];
        g_pexp[bb * 256 + blockIdx.x] = s;
    }
}

// ---- block-wide u64 min (256 threads), deterministic -------------------
__device__ __forceinline__ unsigned long long blockMin64(unsigned long long v,
                                                         unsigned long long* sh8) {
    int warp = threadIdx.x >> 5, lane = threadIdx.x & 31;
    __syncthreads();  // protect sh8 reuse
    #pragma unroll
    for (int o = 16; o; o >>= 1) {
        unsigned long long t = __shfl_down_sync(0xffffffffu, v, o);
        if (t < v) v = t;
    }
    if (lane == 0) sh8[warp] = v;
    __syncthreads();
    if (warp == 0) {
        v = (lane < 8) ? sh8[lane] : ~0ull;
        #pragma unroll
        for (int o = 4; o; o >>= 1) {
            unsigned long long t = __shfl_down_sync(0xffffffffu, v, o);
            if (t < v) v = t;
        }
        if (lane == 0) sh8[0] = v;
    }
    __syncthreads();
    return sh8[0];
}

// ---------------- K2b: per-chunk elementwise + candidate top-n ----------
// grid (CHUNKS, Bv), 256 threads, each thread one float4 (4 elems).
__global__ void __launch_bounds__(256) k2b_elem(const float* __restrict__ w_prev,
                                                const int* __restrict__ n_ptr,
                                                float* __restrict__ out_w) {
    int chunk = blockIdx.x;
    int bb = blockIdx.y;
    int tid = threadIdx.x;
    int warp = tid >> 5, lane = tid & 31;

    __shared__ float shf[8];
    __shared__ unsigned long long sh8[8];

    // redundant deterministic reduction of 256 partials (L2-hot, 1KB)
    float p = g_pexp[bb * 256 + tid];
    #pragma unroll
    for (int o = 16; o; o >>= 1) p += __shfl_down_sync(0xffffffffu, p, o);
    if (lane == 0) shf[warp] = p;
    __syncthreads();
    float tot;
    {
        float t = 0.f;
        #pragma unroll
        for (int i = 0; i < 8; i++) t += shf[i];
        tot = t;  // every thread computes identical value
    }
    float inv = 1.f / tot;

    size_t ebase = (size_t)bb * Nv + (size_t)chunk * CHUNK_ELEMS;
    const float4* e4p  = (const float4*)(g_e + ebase);
    const float4* ww4p = (const float4*)(g_ww + ebase);
    const float4* wu4p = (const float4*)(w_prev + (size_t)bb * 3 * Nv + (size_t)chunk * CHUNK_ELEMS);
    float* ou  = out_w + (size_t)bb * 3 * Nv;          // w_u
    float* orr = ou + Nv;                              // w_r
    float* olu = orr + Nv;                             // w_lu
    size_t obase = (size_t)chunk * CHUNK_ELEMS;

    float4 e4 = e4p[tid];
    float4 ww4 = ww4p[tid];
    float4 wu4 = wu4p[tid];

    float4 wr4, u4;
    wr4.x = e4.x * inv; wr4.y = e4.y * inv; wr4.z = e4.z * inv; wr4.w = e4.w * inv;
    u4.x = GAMMA_C * wu4.x + wr4.x + ww4.x;
    u4.y = GAMMA_C * wu4.y + wr4.y + ww4.y;
    u4.z = GAMMA_C * wu4.z + wr4.z + ww4.z;
    u4.w = GAMMA_C * wu4.w + wr4.w + ww4.w;

    ((float4*)(ou  + obase))[tid] = u4;
    ((float4*)(orr + obase))[tid] = wr4;
    ((float4*)(olu + obase))[tid] = make_float4(0.f, 0.f, 0.f, 0.f);

    // candidate keys: ordered-float bits || global index (tie -> lowest idx)
    int n0 = (int)(chunk * CHUNK_ELEMS) + tid * 4;
    unsigned long long kk[4];
    float uv[4] = {u4.x, u4.y, u4.z, u4.w};
    #pragma unroll
    for (int j = 0; j < 4; j++) {
        unsigned ub = __float_as_uint(uv[j]);
        ub = (ub & 0x80000000u) ? ~ub : (ub | 0x80000000u);
        kk[j] = ((unsigned long long)ub << 32) | (unsigned)(n0 + j);
    }

    int topn = *n_ptr;
    if (topn < 0) topn = 0;
    if (topn > MAXTOPN) topn = MAXTOPN;
    for (int t = 0; t < topn; t++) {
        unsigned long long v = kk[0];
        if (kk[1] < v) v = kk[1];
        if (kk[2] < v) v = kk[2];
        if (kk[3] < v) v = kk[3];
        unsigned long long best = blockMin64(v, sh8);
        if (tid == 0) g_cand[((size_t)bb * CHUNKS + chunk) * MAXTOPN + t] = best;
        #pragma unroll
        for (int j = 0; j < 4; j++) if (kk[j] == best) kk[j] = ~0ull;
    }
}

// ---------------- K3: merge chunk candidates, scatter one-hot ------------
__global__ void __launch_bounds__(256) k3_merge(const int* __restrict__ n_ptr,
                                                float* __restrict__ out_w) {
    int bb = blockIdx.x;
    int tid = threadIdx.x;
    __shared__ unsigned long long sh8[8];

    int topn = *n_ptr;
    if (topn < 0) topn = 0;
    if (topn > MAXTOPN) topn = MAXTOPN;

    unsigned long long key = ~0ull;
    if (tid < CHUNKS * topn) {
        int chunk = tid / topn, slot = tid % topn;
        key = g_cand[((size_t)bb * CHUNKS + chunk) * MAXTOPN + slot];
    }
    float* olu = out_w + (size_t)bb * 3 * Nv + 2 * (size_t)Nv;
    for (int t = 0; t < topn; t++) {
        unsigned long long best = blockMin64(key, sh8);
        if (tid == 0) olu[(int)(best & 0xffffffffu)] = 1.0f;
        if (key == best) key = ~0ull;
    }
}

// ---------------- launch --------------------------------------------------
extern "C" void kernel_launch(void* const* d_in, const int* in_sizes, int n_in,
                              void* d_out, int out_size) {
    const float* emb    = (const float*)d_in[0];  // (B, C)
    const float* w_prev = (const float*)d_in[1];  // (B, 3, N)
    const float* mem    = (const float*)d_in[2];  // (B, N, M)
    const float* W      = (const float*)d_in[3];  // (M+2, C)
    const float* bias   = (const float*)d_in[4];  // (M+2,)
    const int*   n_ptr  = (const int*)d_in[5];    // scalar n

    float* out_w      = (float*)d_out;                       // (B, 3, N)
    float* out_newmem = out_w + (size_t)Bv * 3 * Nv;         // (B, N, M)

    dim3 g0(Mv + 2, Bv);
    k0_head<<<g0, 256>>>(emb, W, bias);
    dim3 g1(Nv / 64, Bv);
    k1_fused<<<g1, 256>>>(mem, w_prev, out_newmem);
    dim3 g2(CHUNKS, Bv);
    k2b_elem<<<g2, 256>>>(w_prev, n_ptr, out_w);
    k3_merge<<<Bv, 256>>>(n_ptr, out_w);
}

// round 6
// speedup vs baseline: 1.3567x; 1.3441x over previous
#include <cuda_runtime.h>
#include <math.h>
#include <stdint.h>

#define Bv 64
#define Nv 16384
#define Mv 64
#define Cv 256
#define GAMMA_C 0.95f
#define EPS_C 1e-16f
#define K1_ROWS 128
#define K1_BLOCKS (Nv / K1_ROWS)   // 128
#define CHUNKS 16
#define CHUNK_ELEMS (Nv / CHUNKS)  // 1024
#define MAXTOPN 16

// ---------------- device scratch (no allocation allowed) ----------------
__device__ float g_k[Bv * Mv];
__device__ float g_beta[Bv];
__device__ float g_g[Bv];
__device__ float g_e[(size_t)Bv * Nv];    // exp(beta * sim)
__device__ float g_ww[(size_t)Bv * Nv];   // w_w
__device__ float g_pexp[Bv * K1_BLOCKS];  // per-k1-block partial sum of exp
__device__ unsigned long long g_cand[Bv * CHUNKS * MAXTOPN];
__device__ int g_ctr[Bv];                 // zero-initialized fan-in counters

// ---------------- K0: o[j,b] = W[j]·emb[b] + b[j] ------------------------
__global__ void __launch_bounds__(256) k0_head(const float* __restrict__ emb,
                                               const float* __restrict__ W,
                                               const float* __restrict__ bias) {
    int j  = blockIdx.x;   // 0..65
    int bb = blockIdx.y;   // batch
    int tid = threadIdx.x;
    int warp = tid >> 5, lane = tid & 31;

    float s = W[j * Cv + tid] * emb[bb * Cv + tid];
    #pragma unroll
    for (int o = 16; o; o >>= 1) s += __shfl_down_sync(0xffffffffu, s, o);
    __shared__ float sh[8];
    if (lane == 0) sh[warp] = s;
    __syncthreads();
    if (tid == 0) {
        float t = 0.f;
        #pragma unroll
        for (int i = 0; i < 8; i++) t += sh[i];
        t += bias[j];
        if (j < Mv) {
            g_k[bb * Mv + j] = t;
        } else if (j == Mv) {
            g_beta[bb] = (t > 0.f) ? (t + log1pf(expf(-t))) : log1pf(expf(t));
        } else {
            g_g[bb] = 1.f / (1.f + expf(-t));
        }
    }
}

// ---------------- K1: fused similarity + exp + w_w + new_memory ----------
// 256 threads; 16 threads per row; 128 rows per block; 8 front-batched loads.
__global__ void __launch_bounds__(256) k1_fused(const float* __restrict__ mem,
                                                const float* __restrict__ w_prev,
                                                float* __restrict__ out_newmem) {
    int bb = blockIdx.y;
    int rowBase = blockIdx.x * K1_ROWS;
    int tid = threadIdx.x;

    __shared__ float sk[Mv];
    __shared__ float sc[2];                  // beta, g
    __shared__ float swp1[K1_ROWS], swp2[K1_ROWS];
    __shared__ float se[K1_ROWS], sww[K1_ROWS];
    __shared__ float swsum[8];

    if (tid < Mv) sk[tid] = g_k[bb * Mv + tid];
    if (tid == 0) { sc[0] = g_beta[bb]; sc[1] = g_g[bb]; }
    if (tid < K1_ROWS)
        swp1[tid] = w_prev[((size_t)bb * 3 + 1) * Nv + rowBase + tid];
    else
        swp2[tid - K1_ROWS] = w_prev[((size_t)bb * 3 + 2) * Nv + rowBase + tid - K1_ROWS];
    __syncthreads();

    int grp = tid >> 4;        // 0..15
    int lane16 = tid & 15;
    float4 k4 = ((const float4*)sk)[lane16];
    float beta = sc[0], g = sc[1];

    float kk = k4.x * k4.x + k4.y * k4.y + k4.z * k4.z + k4.w * k4.w;
    #pragma unroll
    for (int o = 8; o; o >>= 1) kk += __shfl_xor_sync(0xffffffffu, kk, o, 16);
    float knorm = sqrtf(kk);

    size_t base = ((size_t)bb * Nv + rowBase) * Mv;

    // front-batched loads: 8 independent LDG.128 per thread
    float4 v[8];
    #pragma unroll
    for (int it = 0; it < 8; it++)
        v[it] = *(const float4*)(mem + base + (size_t)(it * 16 + grp) * Mv + lane16 * 4);

    float esum = 0.f;
    #pragma unroll
    for (int it = 0; it < 8; it++) {
        float dot = v[it].x * k4.x + v[it].y * k4.y + v[it].z * k4.z + v[it].w * k4.w;
        float ss  = v[it].x * v[it].x + v[it].y * v[it].y + v[it].z * v[it].z + v[it].w * v[it].w;
        #pragma unroll
        for (int o = 8; o; o >>= 1) {
            dot += __shfl_xor_sync(0xffffffffu, dot, o, 16);
            ss  += __shfl_xor_sync(0xffffffffu, ss,  o, 16);
        }
        // all lanes now hold full dot/ss: compute redundantly (warp-wide cost identical)
        int lr = it * 16 + grp;
        float rn = sqrtf(ss);
        float sim = dot / (knorm * rn + EPS_C);
        float e = __expf(beta * sim);
        float ww = g * swp1[lr] + (1.f - g) * swp2[lr];
        if (lane16 == 0) { se[lr] = e; sww[lr] = ww; esum += e; }
        float4 o4;
        o4.x = v[it].x + ww * k4.x;
        o4.y = v[it].y + ww * k4.y;
        o4.z = v[it].z + ww * k4.z;
        o4.w = v[it].w + ww * k4.w;
        *(float4*)(out_newmem + base + (size_t)lr * Mv + lane16 * 4) = o4;
    }

    // block partial exp-sum (deterministic): leaders hold group sums
    esum += __shfl_xor_sync(0xffffffffu, esum, 16);   // lane0 gains lane16's group
    if ((tid & 31) == 0) swsum[tid >> 5] = esum;
    __syncthreads();
    if (tid == 0) {
        float s = 0.f;
        #pragma unroll
        for (int i = 0; i < 8; i++) s += swsum[i];
        g_pexp[bb * K1_BLOCKS + blockIdx.x] = s;
    }
    // coalesced e / ww writes
    if (tid < K1_ROWS) g_e [(size_t)bb * Nv + rowBase + tid] = se[tid];
    else               g_ww[(size_t)bb * Nv + rowBase + tid - K1_ROWS] = sww[tid - K1_ROWS];
}

// ---- block-wide u64 min (256 threads), deterministic -------------------
__device__ __forceinline__ unsigned long long blockMin64(unsigned long long v,
                                                         unsigned long long* sh8) {
    int warp = threadIdx.x >> 5, lane = threadIdx.x & 31;
    __syncthreads();
    #pragma unroll
    for (int o = 16; o; o >>= 1) {
        unsigned long long t = __shfl_down_sync(0xffffffffu, v, o);
        if (t < v) v = t;
    }
    if (lane == 0) sh8[warp] = v;
    __syncthreads();
    if (warp == 0) {
        v = (lane < 8) ? sh8[lane] : ~0ull;
        #pragma unroll
        for (int o = 4; o; o >>= 1) {
            unsigned long long t = __shfl_down_sync(0xffffffffu, v, o);
            if (t < v) v = t;
        }
        if (lane == 0) sh8[0] = v;
    }
    __syncthreads();
    return sh8[0];
}

// -------- K2b: elementwise + per-chunk candidates + fan-in merge ----------
__global__ void __launch_bounds__(256) k2b_elem(const float* __restrict__ w_prev,
                                                const int* __restrict__ n_ptr,
                                                float* __restrict__ out_w) {
    int chunk = blockIdx.x;
    int bb = blockIdx.y;
    int tid = threadIdx.x;
    int warp = tid >> 5, lane = tid & 31;

    __shared__ float shf[4];
    __shared__ unsigned long long sh8[8];
    __shared__ int sLast;

    // deterministic reduction of 128 partials
    float p = (tid < K1_BLOCKS) ? g_pexp[bb * K1_BLOCKS + tid] : 0.f;
    #pragma unroll
    for (int o = 16; o; o >>= 1) p += __shfl_down_sync(0xffffffffu, p, o);
    if (lane == 0 && warp < 4) shf[warp] = p;
    __syncthreads();
    float inv = 1.f / (shf[0] + shf[1] + shf[2] + shf[3]);

    size_t ebase = (size_t)bb * Nv + (size_t)chunk * CHUNK_ELEMS;
    const float4* e4p  = (const float4*)(g_e + ebase);
    const float4* ww4p = (const float4*)(g_ww + ebase);
    const float4* wu4p = (const float4*)(w_prev + (size_t)bb * 3 * Nv + (size_t)chunk * CHUNK_ELEMS);
    float* ou  = out_w + (size_t)bb * 3 * Nv;
    float* orr = ou + Nv;
    float* olu = orr + Nv;
    size_t obase = (size_t)chunk * CHUNK_ELEMS;

    float4 e4 = e4p[tid];
    float4 ww4 = ww4p[tid];
    float4 wu4 = wu4p[tid];

    float4 wr4, u4;
    wr4.x = e4.x * inv; wr4.y = e4.y * inv; wr4.z = e4.z * inv; wr4.w = e4.w * inv;
    u4.x = GAMMA_C * wu4.x + wr4.x + ww4.x;
    u4.y = GAMMA_C * wu4.y + wr4.y + ww4.y;
    u4.z = GAMMA_C * wu4.z + wr4.z + ww4.z;
    u4.w = GAMMA_C * wu4.w + wr4.w + ww4.w;

    ((float4*)(ou  + obase))[tid] = u4;
    ((float4*)(orr + obase))[tid] = wr4;
    ((float4*)(olu + obase))[tid] = make_float4(0.f, 0.f, 0.f, 0.f);

    // candidate keys: ordered-float bits || global index (tie -> lowest idx)
    int n0 = (int)(chunk * CHUNK_ELEMS) + tid * 4;
    unsigned long long kk[4];
    float uv[4] = {u4.x, u4.y, u4.z, u4.w};
    #pragma unroll
    for (int j = 0; j < 4; j++) {
        unsigned ub = __float_as_uint(uv[j]);
        ub = (ub & 0x80000000u) ? ~ub : (ub | 0x80000000u);
        kk[j] = ((unsigned long long)ub << 32) | (unsigned)(n0 + j);
    }

    int topn = *n_ptr;
    if (topn < 0) topn = 0;
    if (topn > MAXTOPN) topn = MAXTOPN;
    for (int t = 0; t < topn; t++) {
        unsigned long long v = kk[0];
        if (kk[1] < v) v = kk[1];
        if (kk[2] < v) v = kk[2];
        if (kk[3] < v) v = kk[3];
        unsigned long long best = blockMin64(v, sh8);
        if (tid == 0) g_cand[((size_t)bb * CHUNKS + chunk) * MAXTOPN + t] = best;
        #pragma unroll
        for (int j = 0; j < 4; j++) if (kk[j] == best) kk[j] = ~0ull;
    }

    // ---- fan-in: last block of this batch merges & scatters one-hot ----
    __threadfence();
    if (tid == 0) sLast = (atomicAdd(&g_ctr[bb], 1) == CHUNKS - 1) ? 1 : 0;
    __syncthreads();
    if (sLast) {
        __threadfence();  // acquire: see all chunks' g_cand and zero-writes
        unsigned long long key = ~0ull;
        if (topn > 0 && tid < CHUNKS * topn) {
            int c = tid / topn, slot = tid % topn;
            key = g_cand[((size_t)bb * CHUNKS + c) * MAXTOPN + slot];
        }
        for (int t = 0; t < topn; t++) {
            unsigned long long best = blockMin64(key, sh8);
            if (tid == 0) olu[(int)(best & 0xffffffffu)] = 1.0f;
            if (key == best) key = ~0ull;
        }
        if (tid == 0) g_ctr[bb] = 0;   // reset for next graph replay
    }
}

// ---------------- launch --------------------------------------------------
extern "C" void kernel_launch(void* const* d_in, const int* in_sizes, int n_in,
                              void* d_out, int out_size) {
    const float* emb    = (const float*)d_in[0];  // (B, C)
    const float* w_prev = (const float*)d_in[1];  // (B, 3, N)
    const float* mem    = (const float*)d_in[2];  // (B, N, M)
    const float* W      = (const float*)d_in[3];  // (M+2, C)
    const float* bias   = (const float*)d_in[4];  // (M+2,)
    const int*   n_ptr  = (const int*)d_in[5];    // scalar n

    float* out_w      = (float*)d_out;                       // (B, 3, N)
    float* out_newmem = out_w + (size_t)Bv * 3 * Nv;         // (B, N, M)

    dim3 g0(Mv + 2, Bv);
    k0_head<<<g0, 256>>>(emb, W, bias);
    dim3 g1(K1_BLOCKS, Bv);
    k1_fused<<<g1, 256>>>(mem, w_prev, out_newmem);
    dim3 g2(CHUNKS, Bv);
    k2b_elem<<<g2, 256>>>(w_prev, n_ptr, out_w);
}

// round 7
// speedup vs baseline: 1.4149x; 1.0429x over previous
#include <cuda_runtime.h>
#include <math.h>
#include <stdint.h>

#define Bv 64
#define Nv 16384
#define Mv 64
#define Cv 256
#define GAMMA_C 0.95f
#define EPS_C 1e-16f
#define K1_ROWS 128
#define K1_BLOCKS (Nv / K1_ROWS)   // 128
#define CHUNKS 16
#define CHUNK_ELEMS (Nv / CHUNKS)  // 1024
#define MAXTOPN 16

#define GRIDDEP_WAIT()   asm volatile("griddepcontrol.wait;" ::: "memory")
#define GRIDDEP_LAUNCH() asm volatile("griddepcontrol.launch_dependents;")

// ---------------- device scratch (no allocation allowed) ----------------
__device__ float g_k[Bv * Mv];
__device__ float g_beta[Bv];
__device__ float g_g[Bv];
__device__ float g_e[(size_t)Bv * Nv];    // exp(beta * sim)
__device__ float g_ww[(size_t)Bv * Nv];   // w_w
__device__ float g_pexp[Bv * K1_BLOCKS];  // per-k1-block partial sum of exp
__device__ unsigned long long g_cand[Bv * CHUNKS * MAXTOPN];
__device__ int g_ctr[Bv];                 // zero-initialized fan-in counters

// ---------------- K0: o[j,b] = W[j]·emb[b] + b[j] ------------------------
__global__ void __launch_bounds__(256) k0_head(const float* __restrict__ emb,
                                               const float* __restrict__ W,
                                               const float* __restrict__ bias) {
    int j  = blockIdx.x;   // 0..65
    int bb = blockIdx.y;   // batch
    int tid = threadIdx.x;
    int warp = tid >> 5, lane = tid & 31;

    float s = W[j * Cv + tid] * emb[bb * Cv + tid];
    #pragma unroll
    for (int o = 16; o; o >>= 1) s += __shfl_down_sync(0xffffffffu, s, o);
    __shared__ float sh[8];
    if (lane == 0) sh[warp] = s;
    __syncthreads();
    if (tid == 0) {
        float t = 0.f;
        #pragma unroll
        for (int i = 0; i < 8; i++) t += sh[i];
        t += bias[j];
        if (j < Mv) {
            g_k[bb * Mv + j] = t;
        } else if (j == Mv) {
            g_beta[bb] = (t > 0.f) ? (t + log1pf(expf(-t))) : log1pf(expf(t));
        } else {
            g_g[bb] = 1.f / (1.f + expf(-t));
        }
    }
    __syncthreads();
    GRIDDEP_LAUNCH();   // let k1 launch; its wait sees our stores
}

// ---------------- K1: fused similarity + exp + w_w + new_memory ----------
// 256 threads; 16 threads per row; 128 rows per block; 8 front-batched loads.
__global__ void __launch_bounds__(256) k1_fused(const float* __restrict__ mem,
                                                const float* __restrict__ w_prev,
                                                float* __restrict__ out_newmem) {
    int bb = blockIdx.y;
    int rowBase = blockIdx.x * K1_ROWS;
    int tid = threadIdx.x;

    __shared__ float sk[Mv];
    __shared__ float sc[2];                  // beta, g
    __shared__ float swp1[K1_ROWS], swp2[K1_ROWS];
    __shared__ float se[K1_ROWS], sww[K1_ROWS];
    __shared__ float swsum[8];

    int grp = tid >> 4;        // 0..15
    int lane16 = tid & 15;
    size_t base = ((size_t)bb * Nv + rowBase) * Mv;

    // ---- independent of k0: issue ALL heavy loads first ----
    float4 v[8];
    #pragma unroll
    for (int it = 0; it < 8; it++)
        v[it] = *(const float4*)(mem + base + (size_t)(it * 16 + grp) * Mv + lane16 * 4);

    if (tid < K1_ROWS)
        swp1[tid] = w_prev[((size_t)bb * 3 + 1) * Nv + rowBase + tid];
    else
        swp2[tid - K1_ROWS] = w_prev[((size_t)bb * 3 + 2) * Nv + rowBase + tid - K1_ROWS];

    // ---- now wait for k0's results ----
    GRIDDEP_WAIT();

    if (tid < Mv) sk[tid] = g_k[bb * Mv + tid];
    if (tid == 0) { sc[0] = g_beta[bb]; sc[1] = g_g[bb]; }
    __syncthreads();

    float4 k4 = ((const float4*)sk)[lane16];
    float beta = sc[0], g = sc[1];

    float kk = k4.x * k4.x + k4.y * k4.y + k4.z * k4.z + k4.w * k4.w;
    #pragma unroll
    for (int o = 8; o; o >>= 1) kk += __shfl_xor_sync(0xffffffffu, kk, o, 16);
    float knorm = sqrtf(kk);

    float esum = 0.f;
    #pragma unroll
    for (int it = 0; it < 8; it++) {
        float dot = v[it].x * k4.x + v[it].y * k4.y + v[it].z * k4.z + v[it].w * k4.w;
        float ss  = v[it].x * v[it].x + v[it].y * v[it].y + v[it].z * v[it].z + v[it].w * v[it].w;
        #pragma unroll
        for (int o = 8; o; o >>= 1) {
            dot += __shfl_xor_sync(0xffffffffu, dot, o, 16);
            ss  += __shfl_xor_sync(0xffffffffu, ss,  o, 16);
        }
        int lr = it * 16 + grp;
        float rn = sqrtf(ss);
        float sim = dot / (knorm * rn + EPS_C);
        float e = __expf(beta * sim);
        float ww = g * swp1[lr] + (1.f - g) * swp2[lr];
        if (lane16 == 0) { se[lr] = e; sww[lr] = ww; esum += e; }
        float4 o4;
        o4.x = v[it].x + ww * k4.x;
        o4.y = v[it].y + ww * k4.y;
        o4.z = v[it].z + ww * k4.z;
        o4.w = v[it].w + ww * k4.w;
        *(float4*)(out_newmem + base + (size_t)lr * Mv + lane16 * 4) = o4;
    }

    // block partial exp-sum (deterministic): leaders hold group sums
    esum += __shfl_xor_sync(0xffffffffu, esum, 16);
    if ((tid & 31) == 0) swsum[tid >> 5] = esum;
    __syncthreads();
    if (tid == 0) {
        float s = 0.f;
        #pragma unroll
        for (int i = 0; i < 8; i++) s += swsum[i];
        g_pexp[bb * K1_BLOCKS + blockIdx.x] = s;
    }
    // coalesced e / ww writes
    if (tid < K1_ROWS) g_e [(size_t)bb * Nv + rowBase + tid] = se[tid];
    else               g_ww[(size_t)bb * Nv + rowBase + tid - K1_ROWS] = sww[tid - K1_ROWS];
    GRIDDEP_LAUNCH();   // let k2b launch
}

// ---- block-wide u64 min (256 threads), deterministic -------------------
__device__ __forceinline__ unsigned long long blockMin64(unsigned long long v,
                                                         unsigned long long* sh8) {
    int warp = threadIdx.x >> 5, lane = threadIdx.x & 31;
    __syncthreads();
    #pragma unroll
    for (int o = 16; o; o >>= 1) {
        unsigned long long t = __shfl_down_sync(0xffffffffu, v, o);
        if (t < v) v = t;
    }
    if (lane == 0) sh8[warp] = v;
    __syncthreads();
    if (warp == 0) {
        v = (lane < 8) ? sh8[lane] : ~0ull;
        #pragma unroll
        for (int o = 4; o; o >>= 1) {
            unsigned long long t = __shfl_down_sync(0xffffffffu, v, o);
            if (t < v) v = t;
        }
        if (lane == 0) sh8[0] = v;
    }
    __syncthreads();
    return sh8[0];
}

// -------- K2b: elementwise + per-chunk candidates + fan-in merge ----------
__global__ void __launch_bounds__(256) k2b_elem(const float* __restrict__ w_prev,
                                                const int* __restrict__ n_ptr,
                                                float* __restrict__ out_w) {
    int chunk = blockIdx.x;
    int bb = blockIdx.y;
    int tid = threadIdx.x;
    int warp = tid >> 5, lane = tid & 31;

    __shared__ float shf[4];
    __shared__ unsigned long long sh8[8];
    __shared__ int sLast;

    float* ou  = out_w + (size_t)bb * 3 * Nv;
    float* orr = ou + Nv;
    float* olu = orr + Nv;
    size_t obase = (size_t)chunk * CHUNK_ELEMS;

    // ---- independent of k1: w_u_prev load, topn load, zero w_lu ----
    const float4* wu4p = (const float4*)(w_prev + (size_t)bb * 3 * Nv + obase);
    float4 wu4 = wu4p[tid];
    int topn = *n_ptr;
    if (topn < 0) topn = 0;
    if (topn > MAXTOPN) topn = MAXTOPN;
    ((float4*)(olu + obase))[tid] = make_float4(0.f, 0.f, 0.f, 0.f);

    // ---- wait for k1 ----
    GRIDDEP_WAIT();

    // deterministic reduction of 128 partials
    float p = (tid < K1_BLOCKS) ? g_pexp[bb * K1_BLOCKS + tid] : 0.f;
    #pragma unroll
    for (int o = 16; o; o >>= 1) p += __shfl_down_sync(0xffffffffu, p, o);
    if (lane == 0 && warp < 4) shf[warp] = p;
    __syncthreads();
    float inv = 1.f / (shf[0] + shf[1] + shf[2] + shf[3]);

    size_t ebase = (size_t)bb * Nv + obase;
    float4 e4  = ((const float4*)(g_e  + ebase))[tid];
    float4 ww4 = ((const float4*)(g_ww + ebase))[tid];

    float4 wr4, u4;
    wr4.x = e4.x * inv; wr4.y = e4.y * inv; wr4.z = e4.z * inv; wr4.w = e4.w * inv;
    u4.x = GAMMA_C * wu4.x + wr4.x + ww4.x;
    u4.y = GAMMA_C * wu4.y + wr4.y + ww4.y;
    u4.z = GAMMA_C * wu4.z + wr4.z + ww4.z;
    u4.w = GAMMA_C * wu4.w + wr4.w + ww4.w;

    ((float4*)(ou  + obase))[tid] = u4;
    ((float4*)(orr + obase))[tid] = wr4;

    // candidate keys: ordered-float bits || global index (tie -> lowest idx)
    int n0 = (int)(chunk * CHUNK_ELEMS) + tid * 4;
    unsigned long long kk[4];
    float uv[4] = {u4.x, u4.y, u4.z, u4.w};
    #pragma unroll
    for (int j = 0; j < 4; j++) {
        unsigned ub = __float_as_uint(uv[j]);
        ub = (ub & 0x80000000u) ? ~ub : (ub | 0x80000000u);
        kk[j] = ((unsigned long long)ub << 32) | (unsigned)(n0 + j);
    }

    for (int t = 0; t < topn; t++) {
        unsigned long long v = kk[0];
        if (kk[1] < v) v = kk[1];
        if (kk[2] < v) v = kk[2];
        if (kk[3] < v) v = kk[3];
        unsigned long long best = blockMin64(v, sh8);
        if (tid == 0) g_cand[((size_t)bb * CHUNKS + chunk) * MAXTOPN + t] = best;
        #pragma unroll
        for (int j = 0; j < 4; j++) if (kk[j] == best) kk[j] = ~0ull;
    }

    // ---- fan-in: last block of this batch merges & scatters one-hot ----
    __threadfence();
    if (tid == 0) sLast = (atomicAdd(&g_ctr[bb], 1) == CHUNKS - 1) ? 1 : 0;
    __syncthreads();
    if (sLast) {
        __threadfence();  // acquire: see all chunks' g_cand and zero-writes
        unsigned long long key = ~0ull;
        if (topn > 0 && tid < CHUNKS * topn) {
            int c = tid / topn, slot = tid % topn;
            key = g_cand[((size_t)bb * CHUNKS + c) * MAXTOPN + slot];
        }
        for (int t = 0; t < topn; t++) {
            unsigned long long best = blockMin64(key, sh8);
            if (tid == 0) olu[(int)(best & 0xffffffffu)] = 1.0f;
            if (key == best) key = ~0ull;
        }
        if (tid == 0) g_ctr[bb] = 0;   // reset for next graph replay
    }
}

// ---------------- launch --------------------------------------------------
static void launch_pdl(void* func, dim3 grid, dim3 block, void** args) {
    cudaLaunchConfig_t cfg = {};
    cfg.gridDim = grid;
    cfg.blockDim = block;
    cfg.dynamicSmemBytes = 0;
    cfg.stream = 0;
    cudaLaunchAttribute attr[1];
    attr[0].id = cudaLaunchAttributeProgrammaticStreamSerialization;
    attr[0].val.programmaticStreamSerializationAllowed = 1;
    cfg.attrs = attr;
    cfg.numAttrs = 1;
    cudaLaunchKernelExC(&cfg, func, args);
}

extern "C" void kernel_launch(void* const* d_in, const int* in_sizes, int n_in,
                              void* d_out, int out_size) {
    const float* emb    = (const float*)d_in[0];  // (B, C)
    const float* w_prev = (const float*)d_in[1];  // (B, 3, N)
    const float* mem    = (const float*)d_in[2];  // (B, N, M)
    const float* W      = (const float*)d_in[3];  // (M+2, C)
    const float* bias   = (const float*)d_in[4];  // (M+2,)
    const int*   n_ptr  = (const int*)d_in[5];    // scalar n

    float* out_w      = (float*)d_out;                       // (B, 3, N)
    float* out_newmem = out_w + (size_t)Bv * 3 * Nv;         // (B, N, M)

    dim3 g0(Mv + 2, Bv);
    k0_head<<<g0, 256>>>(emb, W, bias);

    {
        void* args[] = { (void*)&mem, (void*)&w_prev, (void*)&out_newmem };
        launch_pdl((void*)k1_fused, dim3(K1_BLOCKS, Bv), dim3(256), args);
    }
    {
        void* args[] = { (void*)&w_prev, (void*)&n_ptr, (void*)&out_w };
        launch_pdl((void*)k2b_elem, dim3(CHUNKS, Bv), dim3(256), args);
    }
}

// round 11
// speedup vs baseline: 1.4503x; 1.0250x over previous
#include <cuda_runtime.h>
#include <math.h>
#include <stdint.h>

#define Bv 64
#define Nv 16384
#define Mv 64
#define Cv 256
#define GAMMA_C 0.95f
#define EPS_C 1e-16f
#define K1_ROWS 128
#define K1_BLOCKS (Nv / K1_ROWS)   // 128
#define CHUNKS 16
#define CHUNK_ELEMS (Nv / CHUNKS)  // 1024
#define MAXTOPN 16

#define GRIDDEP_WAIT()   asm volatile("griddepcontrol.wait;" ::: "memory")
#define GRIDDEP_LAUNCH() asm volatile("griddepcontrol.launch_dependents;")

// ---------------- device scratch (no allocation allowed) ----------------
__device__ float g_k[Bv * Mv];
__device__ float g_beta[Bv];
__device__ float g_g[Bv];
__device__ float g_e[(size_t)Bv * Nv];    // exp(beta * sim)
__device__ float g_ww[(size_t)Bv * Nv];   // w_w
__device__ float g_pexp[Bv * K1_BLOCKS];  // per-k1-block partial sum of exp
__device__ unsigned long long g_cand[Bv * CHUNKS * MAXTOPN];
__device__ int g_ctr[Bv];                 // zero-initialized fan-in counters

// ---------------- K0: one block per batch, 8 warps sweep 66 rows ---------
__global__ void __launch_bounds__(256) k0_head(const float* __restrict__ emb,
                                               const float* __restrict__ W,
                                               const float* __restrict__ bias) {
    int bb = blockIdx.x;
    int tid = threadIdx.x;
    int warp = tid >> 5, lane = tid & 31;

    __shared__ float se[Cv];
    se[tid] = emb[bb * Cv + tid];
    __syncthreads();

    for (int j = warp; j < Mv + 2; j += 8) {
        const float* wrow = W + j * Cv;
        float s = 0.f;
        #pragma unroll
        for (int c = 0; c < Cv / 32; c++) s += wrow[lane + c * 32] * se[lane + c * 32];
        #pragma unroll
        for (int o = 16; o; o >>= 1) s += __shfl_down_sync(0xffffffffu, s, o);
        if (lane == 0) {
            float t = s + bias[j];
            if (j < Mv) {
                g_k[bb * Mv + j] = t;
            } else if (j == Mv) {
                g_beta[bb] = (t > 0.f) ? (t + log1pf(expf(-t))) : log1pf(expf(t));
            } else {
                g_g[bb] = 1.f / (1.f + expf(-t));
            }
        }
    }
    __syncthreads();
    GRIDDEP_LAUNCH();   // single wave: fires ~2us in, releases k1 early
}

// ---------------- K1: fused similarity + exp + w_w + new_memory ----------
// 256 threads = 32 groups of 8 lanes; one row per group per iter; 4 iters.
__global__ void __launch_bounds__(256) k1_fused(const float* __restrict__ mem,
                                                const float* __restrict__ w_prev,
                                                float* __restrict__ out_newmem) {
    int bb = blockIdx.y;
    int rowBase = blockIdx.x * K1_ROWS;
    int tid = threadIdx.x;

    __shared__ float sk[Mv];
    __shared__ float sc[2];                  // beta, g
    __shared__ float swp1[K1_ROWS], swp2[K1_ROWS];
    __shared__ float se[K1_ROWS], sww[K1_ROWS];
    __shared__ float swsum[8];

    int grp = tid >> 3;        // 0..31 (row group)
    int lane8 = tid & 7;
    size_t base = ((size_t)bb * Nv + rowBase) * Mv;

    // ---- independent of k0: issue ALL heavy loads first (streaming) ----
    float4 va[4], vb[4];
    #pragma unroll
    for (int it = 0; it < 4; it++) {
        const float4* rp = (const float4*)(mem + base + (size_t)(it * 32 + grp) * Mv);
        va[it] = __ldcs(rp + lane8);
        vb[it] = __ldcs(rp + 8 + lane8);
    }
    if (tid < K1_ROWS)
        swp1[tid] = w_prev[((size_t)bb * 3 + 1) * Nv + rowBase + tid];
    else
        swp2[tid - K1_ROWS] = w_prev[((size_t)bb * 3 + 2) * Nv + rowBase + tid - K1_ROWS];

    // ---- wait for k0's results ----
    GRIDDEP_WAIT();

    if (tid < Mv) sk[tid] = g_k[bb * Mv + tid];
    if (tid == 0) { sc[0] = g_beta[bb]; sc[1] = g_g[bb]; }
    __syncthreads();

    float4 k4a = ((const float4*)sk)[lane8];
    float4 k4b = ((const float4*)sk)[8 + lane8];
    float beta = sc[0], g = sc[1];

    float kk = k4a.x * k4a.x + k4a.y * k4a.y + k4a.z * k4a.z + k4a.w * k4a.w
             + k4b.x * k4b.x + k4b.y * k4b.y + k4b.z * k4b.z + k4b.w * k4b.w;
    #pragma unroll
    for (int o = 4; o; o >>= 1) kk += __shfl_xor_sync(0xffffffffu, kk, o, 8);
    float knorm = sqrtf(kk);

    float esum = 0.f;
    #pragma unroll
    for (int it = 0; it < 4; it++) {
        float dot = va[it].x * k4a.x + va[it].y * k4a.y + va[it].z * k4a.z + va[it].w * k4a.w
                  + vb[it].x * k4b.x + vb[it].y * k4b.y + vb[it].z * k4b.z + vb[it].w * k4b.w;
        float ss  = va[it].x * va[it].x + va[it].y * va[it].y + va[it].z * va[it].z + va[it].w * va[it].w
                  + vb[it].x * vb[it].x + vb[it].y * vb[it].y + vb[it].z * vb[it].z + vb[it].w * vb[it].w;
        #pragma unroll
        for (int o = 4; o; o >>= 1) {
            dot += __shfl_xor_sync(0xffffffffu, dot, o, 8);
            ss  += __shfl_xor_sync(0xffffffffu, ss,  o, 8);
        }
        int lr = it * 32 + grp;
        float rn = sqrtf(ss);
        float sim = dot / (knorm * rn + EPS_C);
        float e = __expf(beta * sim);
        float ww = g * swp1[lr] + (1.f - g) * swp2[lr];
        if (lane8 == 0) { se[lr] = e; sww[lr] = ww; esum += e; }
        float4 o4a, o4b;
        o4a.x = va[it].x + ww * k4a.x;  o4a.y = va[it].y + ww * k4a.y;
        o4a.z = va[it].z + ww * k4a.z;  o4a.w = va[it].w + ww * k4a.w;
        o4b.x = vb[it].x + ww * k4b.x;  o4b.y = vb[it].y + ww * k4b.y;
        o4b.z = vb[it].z + ww * k4b.z;  o4b.w = vb[it].w + ww * k4b.w;
        float4* op = (float4*)(out_newmem + base + (size_t)lr * Mv);
        __stcs(op + lane8, o4a);
        __stcs(op + 8 + lane8, o4b);
    }

    // block partial exp-sum: leaders at lanes 0,8,16,24 hold group sums
    esum += __shfl_xor_sync(0xffffffffu, esum, 16);
    esum += __shfl_xor_sync(0xffffffffu, esum, 8);
    if ((tid & 31) == 0) swsum[tid >> 5] = esum;
    __syncthreads();
    if (tid == 0) {
        float s = 0.f;
        #pragma unroll
        for (int i = 0; i < 8; i++) s += swsum[i];
        g_pexp[bb * K1_BLOCKS + blockIdx.x] = s;
    }
    // coalesced e / ww writes
    if (tid < K1_ROWS) g_e [(size_t)bb * Nv + rowBase + tid] = se[tid];
    else               g_ww[(size_t)bb * Nv + rowBase + tid - K1_ROWS] = sww[tid - K1_ROWS];
    GRIDDEP_LAUNCH();   // let k2b launch
}

// ---- block-wide u64 min (256 threads), deterministic -------------------
__device__ __forceinline__ unsigned long long blockMin64(unsigned long long v,
                                                         unsigned long long* sh8) {
    int warp = threadIdx.x >> 5, lane = threadIdx.x & 31;
    __syncthreads();
    #pragma unroll
    for (int o = 16; o; o >>= 1) {
        unsigned long long t = __shfl_down_sync(0xffffffffu, v, o);
        if (t < v) v = t;
    }
    if (lane == 0) sh8[warp] = v;
    __syncthreads();
    if (warp == 0) {
        v = (lane < 8) ? sh8[lane] : ~0ull;
        #pragma unroll
        for (int o = 4; o; o >>= 1) {
            unsigned long long t = __shfl_down_sync(0xffffffffu, v, o);
            if (t < v) v = t;
        }
        if (lane == 0) sh8[0] = v;
    }
    __syncthreads();
    return sh8[0];
}

// -------- K2b: elementwise + per-chunk candidates + fan-in merge ----------
__global__ void __launch_bounds__(256) k2b_elem(const float* __restrict__ w_prev,
                                                const int* __restrict__ n_ptr,
                                                float* __restrict__ out_w) {
    int chunk = blockIdx.x;
    int bb = blockIdx.y;
    int tid = threadIdx.x;
    int warp = tid >> 5, lane = tid & 31;

    __shared__ float shf[4];
    __shared__ unsigned long long sh8[8];
    __shared__ int sLast;

    float* ou  = out_w + (size_t)bb * 3 * Nv;
    float* orr = ou + Nv;
    float* olu = orr + Nv;
    size_t obase = (size_t)chunk * CHUNK_ELEMS;

    // ---- independent of k1: w_u_prev load, topn load, zero w_lu ----
    float4 wu4 = __ldcs((const float4*)(w_prev + (size_t)bb * 3 * Nv + obase) + tid);
    int topn = *n_ptr;
    if (topn < 0) topn = 0;
    if (topn > MAXTOPN) topn = MAXTOPN;
    __stcs((float4*)(olu + obase) + tid, make_float4(0.f, 0.f, 0.f, 0.f));

    // ---- wait for k1 ----
    GRIDDEP_WAIT();

    // deterministic reduction of 128 partials
    float p = (tid < K1_BLOCKS) ? g_pexp[bb * K1_BLOCKS + tid] : 0.f;
    #pragma unroll
    for (int o = 16; o; o >>= 1) p += __shfl_down_sync(0xffffffffu, p, o);
    if (lane == 0 && warp < 4) shf[warp] = p;
    __syncthreads();
    float inv = 1.f / (shf[0] + shf[1] + shf[2] + shf[3]);

    size_t ebase = (size_t)bb * Nv + obase;
    float4 e4  = __ldcs((const float4*)(g_e  + ebase) + tid);
    float4 ww4 = __ldcs((const float4*)(g_ww + ebase) + tid);

    float4 wr4, u4;
    wr4.x = e4.x * inv; wr4.y = e4.y * inv; wr4.z = e4.z * inv; wr4.w = e4.w * inv;
    u4.x = GAMMA_C * wu4.x + wr4.x + ww4.x;
    u4.y = GAMMA_C * wu4.y + wr4.y + ww4.y;
    u4.z = GAMMA_C * wu4.z + wr4.z + ww4.z;
    u4.w = GAMMA_C * wu4.w + wr4.w + ww4.w;

    __stcs((float4*)(ou  + obase) + tid, u4);
    __stcs((float4*)(orr + obase) + tid, wr4);

    // candidate keys: ordered-float bits || global index (tie -> lowest idx)
    int n0 = (int)(chunk * CHUNK_ELEMS) + tid * 4;
    unsigned long long kk[4];
    float uv[4] = {u4.x, u4.y, u4.z, u4.w};
    #pragma unroll
    for (int j = 0; j < 4; j++) {
        unsigned ub = __float_as_uint(uv[j]);
        ub = (ub & 0x80000000u) ? ~ub : (ub | 0x80000000u);
        kk[j] = ((unsigned long long)ub << 32) | (unsigned)(n0 + j);
    }

    for (int t = 0; t < topn; t++) {
        unsigned long long v = kk[0];
        if (kk[1] < v) v = kk[1];
        if (kk[2] < v) v = kk[2];
        if (kk[3] < v) v = kk[3];
        unsigned long long best = blockMin64(v, sh8);
        if (tid == 0) g_cand[((size_t)bb * CHUNKS + chunk) * MAXTOPN + t] = best;
        #pragma unroll
        for (int j = 0; j < 4; j++) if (kk[j] == best) kk[j] = ~0ull;
    }

    // ---- fan-in: last block of this batch merges & scatters one-hot ----
    __threadfence();
    if (tid == 0) sLast = (atomicAdd(&g_ctr[bb], 1) == CHUNKS - 1) ? 1 : 0;
    __syncthreads();
    if (sLast) {
        __threadfence();  // acquire: see all chunks' g_cand and zero-writes
        unsigned long long key = ~0ull;
        if (topn > 0 && tid < CHUNKS * topn) {
            int c = tid / topn, slot = tid % topn;
            key = g_cand[((size_t)bb * CHUNKS + c) * MAXTOPN + slot];
        }
        for (int t = 0; t < topn; t++) {
            unsigned long long best = blockMin64(key, sh8);
            if (tid == 0) olu[(int)(best & 0xffffffffu)] = 1.0f;
            if (key == best) key = ~0ull;
        }
        if (tid == 0) g_ctr[bb] = 0;   // reset for next graph replay
    }
}

// ---------------- launch --------------------------------------------------
static void launch_pdl(void* func, dim3 grid, dim3 block, void** args) {
    cudaLaunchConfig_t cfg = {};
    cfg.gridDim = grid;
    cfg.blockDim = block;
    cfg.dynamicSmemBytes = 0;
    cfg.stream = 0;
    cudaLaunchAttribute attr[1];
    attr[0].id = cudaLaunchAttributeProgrammaticStreamSerialization;
    attr[0].val.programmaticStreamSerializationAllowed = 1;
    cfg.attrs = attr;
    cfg.numAttrs = 1;
    cudaLaunchKernelExC(&cfg, func, args);
}

extern "C" void kernel_launch(void* const* d_in, const int* in_sizes, int n_in,
                              void* d_out, int out_size) {
    const float* emb    = (const float*)d_in[0];  // (B, C)
    const float* w_prev = (const float*)d_in[1];  // (B, 3, N)
    const float* mem    = (const float*)d_in[2];  // (B, N, M)
    const float* W      = (const float*)d_in[3];  // (M+2, C)
    const float* bias   = (const float*)d_in[4];  // (M+2,)
    const int*   n_ptr  = (const int*)d_in[5];    // scalar n

    float* out_w      = (float*)d_out;                       // (B, 3, N)
    float* out_newmem = out_w + (size_t)Bv * 3 * Nv;         // (B, N, M)

    k0_head<<<Bv, 256>>>(emb, W, bias);

    {
        void* args[] = { (void*)&mem, (void*)&w_prev, (void*)&out_newmem };
        launch_pdl((void*)k1_fused, dim3(K1_BLOCKS, Bv), dim3(256), args);
    }
    {
        void* args[] = { (void*)&w_prev, (void*)&n_ptr, (void*)&out_w };
        launch_pdl((void*)k2b_elem, dim3(CHUNKS, Bv), dim3(256), args);
    }
}